// round 15
// baseline (speedup 1.0000x reference)
#include <cuda_runtime.h>
#include <cuda_bf16.h>
#include <math.h>

#define NN 100000
#define NE 1000000
#define HID 64
#define NC 30
#define CP 32
#define REGC 0.01
#define NB 391        // ceil(NN/256)
#define EB 3907       // ceil(NE/256)
#define GB 592        // gemm1 blocks

// ---------------- scratch (static device globals; no allocation) ----------------
__device__ __align__(16) float g_deg[NN];
__device__ __align__(16) float g_dinv[NN];
__device__ __align__(16) float g_h1[NN * HID];     // x @ W1
__device__ __align__(16) float g_h2[NN * CP];      // layer2 pre-agg (padded)
__device__ __align__(16) float g_fxp[NN * CP];     // padded softmax output
__device__ __align__(16) uint2 g_csr[NE];          // {src, bitcast(norm)} sorted by dst
__device__ int g_cnt[NN];
__device__ int g_rowstart[NN + 1];
__device__ int g_cursor[NN];
__device__ int g_blocksum[NB];
__device__ float g_S[CP];
__device__ double g_mse;
__device__ int g_is64;
__device__ int g_done;

__device__ __forceinline__ int load_idx(const void* ei, int is64, int pos) {
    if (is64) return (int)((const long long*)ei)[pos];
    return ((const int*)ei)[pos];
}

// ---------------- kernels ----------------

// init scratch + detect edge_index dtype (block 0 thread 0; reads first 2KB only)
__global__ void init_kernel(const void* ei) {
    int n = blockIdx.x * blockDim.x + threadIdx.x;
    if (n == 0) {
        const long long* e64 = (const long long*)ei;
        int ok64 = 1;
        for (int i = 0; i < 256; i++) {
            long long v = e64[i];
            if (v < 0 || v >= NN) { ok64 = 0; break; }
        }
        g_is64 = ok64;
        g_mse = 0.0;
        g_done = 0;
    }
    if (n < NN) {
        g_deg[n] = 1.0f;     // self-loop
        g_cnt[n] = 0;
    }
    if (n < CP) g_S[n] = 0.f;
}

// Dual-role kernel: blocks [0,EB) do deg+hist; blocks [EB,EB+GB) do gemm1.
// gemm1 depends only on x/W1 and overlaps the edge histogram.
__global__ void deghist_gemm1_kernel(const void* __restrict__ ei,
                                     const float* __restrict__ w,
                                     const float* __restrict__ x,
                                     const float* __restrict__ W1) {
    if (blockIdx.x < EB) {
        int e = blockIdx.x * blockDim.x + threadIdx.x;
        if (e >= NE) return;
        int is64 = g_is64;
        int dst = load_idx(ei, is64, NE + e);
        atomicAdd(&g_deg[dst], w[e]);
        atomicAdd(&g_cnt[dst], 1);
    } else {
        __shared__ float Ws[64 * 64];
        for (int i = threadIdx.x; i < 64 * 64; i += blockDim.x) Ws[i] = W1[i];
        __syncthreads();
        int bid = blockIdx.x - EB;
        int gw = (bid * blockDim.x + threadIdx.x) >> 5;
        int lane = threadIdx.x & 31;
        int nw = (GB * blockDim.x) >> 5;
        for (int n = gw; n < NN; n += nw) {
            float x0 = x[n * 64 + lane];
            float x1 = x[n * 64 + 32 + lane];
            float a0 = 0.f, a1 = 0.f;
#pragma unroll
            for (int k = 0; k < 32; k++) {
                float xk = __shfl_sync(0xffffffffu, x0, k);
                a0 += xk * Ws[k * 64 + lane];
                a1 += xk * Ws[k * 64 + 32 + lane];
            }
#pragma unroll
            for (int k = 0; k < 32; k++) {
                float xk = __shfl_sync(0xffffffffu, x1, k);
                a0 += xk * Ws[(k + 32) * 64 + lane];
                a1 += xk * Ws[(k + 32) * 64 + 32 + lane];
            }
            g_h1[n * 64 + lane] = a0;
            g_h1[n * 64 + 32 + lane] = a1;
        }
    }
}

// per-block count reduction, fused with dinv computation
__global__ void scan1_kernel() {
    __shared__ int s[256];
    int n = blockIdx.x * 256 + threadIdx.x;
    if (n < NN) g_dinv[n] = rsqrtf(g_deg[n]);
    s[threadIdx.x] = (n < NN) ? g_cnt[n] : 0;
    __syncthreads();
    for (int o = 128; o > 0; o >>= 1) {
        if (threadIdx.x < o) s[threadIdx.x] += s[threadIdx.x + o];
        __syncthreads();
    }
    if (threadIdx.x == 0) g_blocksum[blockIdx.x] = s[0];
}

// merged top+final scan: each block redundantly reduces its predecessors'
// block sums (<=391 int reads) then does its local tile scan.
__global__ void scan2_kernel() {
    __shared__ int r[256];
    __shared__ int s[256];
    int tid = threadIdx.x;
    // exclusive prefix over predecessor blocks
    int base = 0;
    for (int i = tid; i < blockIdx.x; i += 256) base += g_blocksum[i];
    r[tid] = base;
    __syncthreads();
    for (int o = 128; o > 0; o >>= 1) {
        if (tid < o) r[tid] += r[tid + o];
        __syncthreads();
    }
    base = r[0];
    // local inclusive scan of this tile
    int n = blockIdx.x * 256 + tid;
    int v = (n < NN) ? g_cnt[n] : 0;
    s[tid] = v;
    __syncthreads();
    for (int o = 1; o < 256; o <<= 1) {
        int t = (tid >= o) ? s[tid - o] : 0;
        __syncthreads();
        s[tid] += t;
        __syncthreads();
    }
    if (n < NN) {
        int excl = base + s[tid] - v;
        g_rowstart[n] = excl;
        g_cursor[n] = excl;
        if (n == NN - 1) g_rowstart[NN] = excl + v;
    }
}

// bucket edges by dst: csr[pos] = {src, norm}
__global__ void fill_kernel(const void* __restrict__ ei,
                            const float* __restrict__ w) {
    int e = blockIdx.x * blockDim.x + threadIdx.x;
    if (e >= NE) return;
    int is64 = g_is64;
    int src = load_idx(ei, is64, e);
    int dst = load_idx(ei, is64, NE + e);
    float nm = g_dinv[src] * w[e] * g_dinv[dst];
    int pos = atomicAdd(&g_cursor[dst], 1);
    g_csr[pos] = make_uint2((unsigned)src, __float_as_uint(nm));
}

// CSR gather layer1 fused with self-loop+bias+relu AND gemm2 (h @ W2).
// Warp per node; h row stays in registers, h2 written directly.
__global__ void gather1_gemm2_kernel(const float* __restrict__ b1,
                                     const float* __restrict__ W2) {
    __shared__ float Ws[64 * CP];
    for (int i = threadIdx.x; i < 64 * CP; i += blockDim.x) {
        int k = i / CP, c = i % CP;
        Ws[i] = (c < NC) ? W2[k * NC + c] : 0.f;
    }
    __syncthreads();
    int gw = (blockIdx.x * blockDim.x + threadIdx.x) >> 5;
    int lane = threadIdx.x & 31;
    if (gw >= NN) return;
    int n = gw;
    int beg = g_rowstart[n], end = g_rowstart[n + 1];
    float a0 = 0.f, a1 = 0.f;
    int i = beg;
    for (; i + 1 < end; i += 2) {
        uint2 p0 = g_csr[i];
        uint2 p1 = g_csr[i + 1];
        float nm0 = __uint_as_float(p0.y);
        float nm1 = __uint_as_float(p1.y);
        const float* r0 = g_h1 + p0.x * 64;
        const float* r1 = g_h1 + p1.x * 64;
        float v00 = r0[lane], v01 = r0[32 + lane];
        float v10 = r1[lane], v11 = r1[32 + lane];
        a0 += nm0 * v00 + nm1 * v10;
        a1 += nm0 * v01 + nm1 * v11;
    }
    if (i < end) {
        uint2 p = g_csr[i];
        float nm = __uint_as_float(p.y);
        a0 += nm * g_h1[p.x * 64 + lane];
        a1 += nm * g_h1[p.x * 64 + 32 + lane];
    }
    float invdeg = g_dinv[n] * g_dinv[n];
    a0 = fmaxf(a0 + g_h1[n * 64 + lane] * invdeg + b1[lane], 0.f);
    a1 = fmaxf(a1 + g_h1[n * 64 + 32 + lane] * invdeg + b1[32 + lane], 0.f);
    // h2[n][lane] = sum_k h[k] * W2[k][lane]
    float acc = 0.f;
#pragma unroll
    for (int k = 0; k < 32; k++) {
        float hk = __shfl_sync(0xffffffffu, a0, k);
        acc += hk * Ws[k * CP + lane];
    }
#pragma unroll
    for (int k = 0; k < 32; k++) {
        float hk = __shfl_sync(0xffffffffu, a1, k);
        acc += hk * Ws[(k + 32) * CP + lane];
    }
    g_h2[n * CP + lane] = acc;
}

// CSR gather layer2 fused with softmax, FX output and S accumulation.
__global__ void gather2_softmax_kernel(const float* __restrict__ b2,
                                       float* __restrict__ out) {
    int gw = (blockIdx.x * blockDim.x + threadIdx.x) >> 5;
    int lane = threadIdx.x & 31;
    int nw = (gridDim.x * blockDim.x) >> 5;
    bool valid = (lane < NC);
    float bc = valid ? b2[lane] : 0.f;
    float s_local = 0.f;
    for (int n = gw; n < NN; n += nw) {
        int beg = g_rowstart[n], end = g_rowstart[n + 1];
        float acc = 0.f;
        int i = beg;
        for (; i + 1 < end; i += 2) {
            uint2 p0 = g_csr[i];
            uint2 p1 = g_csr[i + 1];
            acc += __uint_as_float(p0.y) * g_h2[p0.x * CP + lane]
                 + __uint_as_float(p1.y) * g_h2[p1.x * CP + lane];
        }
        if (i < end) {
            uint2 p = g_csr[i];
            acc += __uint_as_float(p.y) * g_h2[p.x * CP + lane];
        }
        float invdeg = g_dinv[n] * g_dinv[n];
        float xv = valid ? (acc + g_h2[n * CP + lane] * invdeg + bc) : -INFINITY;
        float m = xv;
#pragma unroll
        for (int o = 16; o > 0; o >>= 1)
            m = fmaxf(m, __shfl_xor_sync(0xffffffffu, m, o));
        float ev = valid ? expf(xv - m) : 0.f;
        float s = ev;
#pragma unroll
        for (int o = 16; o > 0; o >>= 1)
            s += __shfl_xor_sync(0xffffffffu, s, o);
        float fx = ev / s;
        g_fxp[n * CP + lane] = valid ? fx : 0.f;
        if (valid) {
            out[n * NC + lane] = fx;
            s_local += log1pf(-fx * fx);
        }
    }
    if (valid) atomicAdd(&g_S[lane], s_local);
}

// Coalesced edge loss: warp = 4 groups of 8 lanes; each group handles one edge,
// reading each 128B FX row as 8 lanes x float4 (fully coalesced).
// Fused finalize via last-block-done counter.
#define ELB 1184
__global__ void edgeloss_kernel(const void* __restrict__ ei,
                                const float* __restrict__ w,
                                float* __restrict__ out) {
    __shared__ float sred[256];
    int tid = threadIdx.x;
    int lane = tid & 31;
    int group = lane >> 3;        // 0..3
    int gl = lane & 7;            // 0..7
    int gwarp = (blockIdx.x * blockDim.x + tid) >> 5;
    int nwarp = (gridDim.x * blockDim.x) >> 5;
    int is64 = g_is64;
    float local = 0.f;
    for (int e = gwarp * 4 + group; e < NE; e += nwarp * 4) {
        int src = load_idx(ei, is64, e);
        int dst = load_idx(ei, is64, NE + e);
        float4 a = ((const float4*)g_fxp)[src * 8 + gl];
        float4 b = ((const float4*)g_fxp)[dst * 8 + gl];
        float s = a.x * b.x + a.y * b.y + a.z * b.z + a.w * b.w;
        s += __shfl_xor_sync(0xffffffffu, s, 4);
        s += __shfl_xor_sync(0xffffffffu, s, 2);
        s += __shfl_xor_sync(0xffffffffu, s, 1);
        if (gl == 0) {
            float d = s - w[e];
            local += d * d;
        }
    }
    sred[tid] = local;
    __syncthreads();
    for (int o = 128; o > 0; o >>= 1) {
        if (tid < o) sred[tid] += sred[tid + o];
        __syncthreads();
    }
    if (tid == 0) {
        atomicAdd(&g_mse, (double)sred[0]);
        __threadfence();
        int prev = atomicAdd(&g_done, 1);
        if (prev == ELB - 1) {                 // last block finalizes
            g_done = 0;
            double preg = 0.0;
            for (int c = 0; c < NC; c++) {
                double sc = (double)g_S[c];
                preg += -log(1.0001 - exp(sc));
            }
            double loss = g_mse / (double)NE + REGC * preg;
            out[NN * NC] = (float)loss;
        }
    }
}

// ---------------- launch ----------------
extern "C" void kernel_launch(void* const* d_in, const int* in_sizes, int n_in,
                              void* d_out, int out_size) {
    const float* x = (const float*)d_in[0];
    const void* ei = (const void*)d_in[1];
    const float* ea = (const float*)d_in[2];
    const float* W1 = (const float*)d_in[3];
    const float* b1 = (const float*)d_in[4];
    const float* W2 = (const float*)d_in[5];
    const float* b2 = (const float*)d_in[6];
    float* out = (float*)d_out;

    const int T = 256;
    init_kernel<<<NB, T>>>(ei);
    deghist_gemm1_kernel<<<EB + GB, T>>>(ei, ea, x, W1);
    scan1_kernel<<<NB, T>>>();
    scan2_kernel<<<NB, T>>>();
    fill_kernel<<<EB, T>>>(ei, ea);
    gather1_gemm2_kernel<<<(NN * 32 + T - 1) / T, T>>>(b1, W2);
    gather2_softmax_kernel<<<592, T>>>(b2, out);
    edgeloss_kernel<<<ELB, T>>>(ei, ea, out);
}

// round 16
// speedup vs baseline: 1.1335x; 1.1335x over previous
#include <cuda_runtime.h>
#include <cuda_bf16.h>
#include <math.h>

#define NN 100000
#define NE 1000000
#define HID 64
#define NC 30
#define CP 32
#define REGC 0.01
#define NB 391        // ceil(NN/256)
#define EB 3907       // ceil(NE/256)

// ---------------- scratch (static device globals; no allocation) ----------------
__device__ __align__(16) float g_deg[NN];
__device__ __align__(16) float g_dinv[NN];
__device__ __align__(16) float g_h1[NN * HID];     // x @ W1
__device__ __align__(16) float g_h2[NN * CP];      // layer2 pre-agg (padded)
__device__ __align__(16) float g_fxp[NN * CP];     // padded softmax output
__device__ __align__(16) uint2 g_csr[NE];          // {src, bitcast(norm)} sorted by dst
__device__ int g_cnt[NN];
__device__ int g_rowstart[NN + 1];
__device__ int g_cursor[NN];
__device__ int g_blocksum[NB];
__device__ float g_S[CP];
__device__ double g_mse;
__device__ int g_is64;
__device__ int g_done;

__device__ __forceinline__ int load_idx(const void* ei, int is64, int pos) {
    if (is64) return (int)((const long long*)ei)[pos];
    return ((const int*)ei)[pos];
}

// ---------------- kernels ----------------

// init scratch + detect edge_index dtype (block 0 thread 0; reads first 2KB only)
__global__ void init_kernel(const void* ei) {
    int n = blockIdx.x * blockDim.x + threadIdx.x;
    if (n == 0) {
        const long long* e64 = (const long long*)ei;
        int ok64 = 1;
        for (int i = 0; i < 256; i++) {
            long long v = e64[i];
            if (v < 0 || v >= NN) { ok64 = 0; break; }
        }
        g_is64 = ok64;
        g_mse = 0.0;
        g_done = 0;
    }
    if (n < NN) {
        g_deg[n] = 1.0f;     // self-loop
        g_cnt[n] = 0;
    }
    if (n < CP) g_S[n] = 0.f;
}

// deg (weighted) + dst histogram in one pass
__global__ void deg_hist_kernel(const void* __restrict__ ei,
                                const float* __restrict__ w) {
    int e = blockIdx.x * blockDim.x + threadIdx.x;
    if (e >= NE) return;
    int is64 = g_is64;
    int dst = load_idx(ei, is64, NE + e);
    atomicAdd(&g_deg[dst], w[e]);
    atomicAdd(&g_cnt[dst], 1);
}

// per-block count reduction, fused with dinv computation
__global__ void scan1_kernel() {
    __shared__ int s[256];
    int n = blockIdx.x * 256 + threadIdx.x;
    if (n < NN) g_dinv[n] = rsqrtf(g_deg[n]);
    s[threadIdx.x] = (n < NN) ? g_cnt[n] : 0;
    __syncthreads();
    for (int o = 128; o > 0; o >>= 1) {
        if (threadIdx.x < o) s[threadIdx.x] += s[threadIdx.x + o];
        __syncthreads();
    }
    if (threadIdx.x == 0) g_blocksum[blockIdx.x] = s[0];
}

// merged top+final scan: each block redundantly reduces its predecessors'
// block sums (<=391 int reads) then does its local tile scan.
__global__ void scan2_kernel() {
    __shared__ int r[256];
    __shared__ int s[256];
    int tid = threadIdx.x;
    int base = 0;
    for (int i = tid; i < blockIdx.x; i += 256) base += g_blocksum[i];
    r[tid] = base;
    __syncthreads();
    for (int o = 128; o > 0; o >>= 1) {
        if (tid < o) r[tid] += r[tid + o];
        __syncthreads();
    }
    base = r[0];
    int n = blockIdx.x * 256 + tid;
    int v = (n < NN) ? g_cnt[n] : 0;
    s[tid] = v;
    __syncthreads();
    for (int o = 1; o < 256; o <<= 1) {
        int t = (tid >= o) ? s[tid - o] : 0;
        __syncthreads();
        s[tid] += t;
        __syncthreads();
    }
    if (n < NN) {
        int excl = base + s[tid] - v;
        g_rowstart[n] = excl;
        g_cursor[n] = excl;
        if (n == NN - 1) g_rowstart[NN] = excl + v;
    }
}

// bucket edges by dst: csr[pos] = {src, norm}
__global__ void fill_kernel(const void* __restrict__ ei,
                            const float* __restrict__ w) {
    int e = blockIdx.x * blockDim.x + threadIdx.x;
    if (e >= NE) return;
    int is64 = g_is64;
    int src = load_idx(ei, is64, e);
    int dst = load_idx(ei, is64, NE + e);
    float nm = g_dinv[src] * w[e] * g_dinv[dst];
    int pos = atomicAdd(&g_cursor[dst], 1);
    g_csr[pos] = make_uint2((unsigned)src, __float_as_uint(nm));
}

// h1 = x @ W1  (warp per node, W1 in smem)
__global__ void gemm1_kernel(const float* __restrict__ x,
                             const float* __restrict__ W1) {
    __shared__ float Ws[64 * 64];
    for (int i = threadIdx.x; i < 64 * 64; i += blockDim.x) Ws[i] = W1[i];
    __syncthreads();
    int gw = (blockIdx.x * blockDim.x + threadIdx.x) >> 5;
    int lane = threadIdx.x & 31;
    int nw = (gridDim.x * blockDim.x) >> 5;
    for (int n = gw; n < NN; n += nw) {
        float x0 = x[n * 64 + lane];
        float x1 = x[n * 64 + 32 + lane];
        float a0 = 0.f, a1 = 0.f;
#pragma unroll
        for (int k = 0; k < 32; k++) {
            float xk = __shfl_sync(0xffffffffu, x0, k);
            a0 += xk * Ws[k * 64 + lane];
            a1 += xk * Ws[k * 64 + 32 + lane];
        }
#pragma unroll
        for (int k = 0; k < 32; k++) {
            float xk = __shfl_sync(0xffffffffu, x1, k);
            a0 += xk * Ws[(k + 32) * 64 + lane];
            a1 += xk * Ws[(k + 32) * 64 + 32 + lane];
        }
        g_h1[n * 64 + lane] = a0;
        g_h1[n * 64 + 32 + lane] = a1;
    }
}

// CSR gather layer1 fused with self-loop+bias+relu AND gemm2 (h @ W2).
// Warp per node; h row stays in registers, h2 written directly. 4-way unroll.
__global__ void gather1_gemm2_kernel(const float* __restrict__ b1,
                                     const float* __restrict__ W2) {
    __shared__ float Ws[64 * CP];
    for (int i = threadIdx.x; i < 64 * CP; i += blockDim.x) {
        int k = i / CP, c = i % CP;
        Ws[i] = (c < NC) ? W2[k * NC + c] : 0.f;
    }
    __syncthreads();
    int gw = (blockIdx.x * blockDim.x + threadIdx.x) >> 5;
    int lane = threadIdx.x & 31;
    if (gw >= NN) return;
    int n = gw;
    int beg = g_rowstart[n], end = g_rowstart[n + 1];
    float a0 = 0.f, a1 = 0.f;
    int i = beg;
    for (; i + 3 < end; i += 4) {
        uint2 p0 = g_csr[i];
        uint2 p1 = g_csr[i + 1];
        uint2 p2 = g_csr[i + 2];
        uint2 p3 = g_csr[i + 3];
        const float* r0 = g_h1 + p0.x * 64;
        const float* r1 = g_h1 + p1.x * 64;
        const float* r2 = g_h1 + p2.x * 64;
        const float* r3 = g_h1 + p3.x * 64;
        float v00 = r0[lane], v01 = r0[32 + lane];
        float v10 = r1[lane], v11 = r1[32 + lane];
        float v20 = r2[lane], v21 = r2[32 + lane];
        float v30 = r3[lane], v31 = r3[32 + lane];
        float nm0 = __uint_as_float(p0.y);
        float nm1 = __uint_as_float(p1.y);
        float nm2 = __uint_as_float(p2.y);
        float nm3 = __uint_as_float(p3.y);
        a0 += nm0 * v00 + nm1 * v10 + nm2 * v20 + nm3 * v30;
        a1 += nm0 * v01 + nm1 * v11 + nm2 * v21 + nm3 * v31;
    }
    for (; i < end; i++) {
        uint2 p = g_csr[i];
        float nm = __uint_as_float(p.y);
        a0 += nm * g_h1[p.x * 64 + lane];
        a1 += nm * g_h1[p.x * 64 + 32 + lane];
    }
    float invdeg = g_dinv[n] * g_dinv[n];
    a0 = fmaxf(a0 + g_h1[n * 64 + lane] * invdeg + b1[lane], 0.f);
    a1 = fmaxf(a1 + g_h1[n * 64 + 32 + lane] * invdeg + b1[32 + lane], 0.f);
    // h2[n][lane] = sum_k h[k] * W2[k][lane]
    float acc = 0.f;
#pragma unroll
    for (int k = 0; k < 32; k++) {
        float hk = __shfl_sync(0xffffffffu, a0, k);
        acc += hk * Ws[k * CP + lane];
    }
#pragma unroll
    for (int k = 0; k < 32; k++) {
        float hk = __shfl_sync(0xffffffffu, a1, k);
        acc += hk * Ws[(k + 32) * CP + lane];
    }
    g_h2[n * CP + lane] = acc;
}

// CSR gather layer2 fused with softmax, FX output and S accumulation.
__global__ void gather2_softmax_kernel(const float* __restrict__ b2,
                                       float* __restrict__ out) {
    int gw = (blockIdx.x * blockDim.x + threadIdx.x) >> 5;
    int lane = threadIdx.x & 31;
    int nw = (gridDim.x * blockDim.x) >> 5;
    bool valid = (lane < NC);
    float bc = valid ? b2[lane] : 0.f;
    float s_local = 0.f;
    for (int n = gw; n < NN; n += nw) {
        int beg = g_rowstart[n], end = g_rowstart[n + 1];
        float acc = 0.f;
        int i = beg;
        for (; i + 1 < end; i += 2) {
            uint2 p0 = g_csr[i];
            uint2 p1 = g_csr[i + 1];
            acc += __uint_as_float(p0.y) * g_h2[p0.x * CP + lane]
                 + __uint_as_float(p1.y) * g_h2[p1.x * CP + lane];
        }
        if (i < end) {
            uint2 p = g_csr[i];
            acc += __uint_as_float(p.y) * g_h2[p.x * CP + lane];
        }
        float invdeg = g_dinv[n] * g_dinv[n];
        float xv = valid ? (acc + g_h2[n * CP + lane] * invdeg + bc) : -INFINITY;
        float m = xv;
#pragma unroll
        for (int o = 16; o > 0; o >>= 1)
            m = fmaxf(m, __shfl_xor_sync(0xffffffffu, m, o));
        float ev = valid ? expf(xv - m) : 0.f;
        float s = ev;
#pragma unroll
        for (int o = 16; o > 0; o >>= 1)
            s += __shfl_xor_sync(0xffffffffu, s, o);
        float fx = ev / s;
        g_fxp[n * CP + lane] = valid ? fx : 0.f;
        if (valid) {
            out[n * NC + lane] = fx;
            s_local += log1pf(-fx * fx);
        }
    }
    if (valid) atomicAdd(&g_S[lane], s_local);
}

// Coalesced edge loss: warp = 4 groups of 8 lanes; each group handles one edge,
// reading each 128B FX row as 8 lanes x float4 (fully coalesced).
// Fused finalize via last-block-done counter.
#define ELB 1184
__global__ void edgeloss_kernel(const void* __restrict__ ei,
                                const float* __restrict__ w,
                                float* __restrict__ out) {
    __shared__ float sred[256];
    int tid = threadIdx.x;
    int lane = tid & 31;
    int group = lane >> 3;        // 0..3
    int gl = lane & 7;            // 0..7
    int gwarp = (blockIdx.x * blockDim.x + tid) >> 5;
    int nwarp = (gridDim.x * blockDim.x) >> 5;
    int is64 = g_is64;
    float local = 0.f;
    for (int e = gwarp * 4 + group; e < NE; e += nwarp * 4) {
        int src = load_idx(ei, is64, e);
        int dst = load_idx(ei, is64, NE + e);
        float4 a = ((const float4*)g_fxp)[src * 8 + gl];
        float4 b = ((const float4*)g_fxp)[dst * 8 + gl];
        float s = a.x * b.x + a.y * b.y + a.z * b.z + a.w * b.w;
        s += __shfl_xor_sync(0xffffffffu, s, 4);
        s += __shfl_xor_sync(0xffffffffu, s, 2);
        s += __shfl_xor_sync(0xffffffffu, s, 1);
        if (gl == 0) {
            float d = s - w[e];
            local += d * d;
        }
    }
    sred[tid] = local;
    __syncthreads();
    for (int o = 128; o > 0; o >>= 1) {
        if (tid < o) sred[tid] += sred[tid + o];
        __syncthreads();
    }
    if (tid == 0) {
        atomicAdd(&g_mse, (double)sred[0]);
        __threadfence();
        int prev = atomicAdd(&g_done, 1);
        if (prev == ELB - 1) {                 // last block finalizes
            g_done = 0;
            double preg = 0.0;
            for (int c = 0; c < NC; c++) {
                double sc = (double)g_S[c];
                preg += -log(1.0001 - exp(sc));
            }
            double loss = g_mse / (double)NE + REGC * preg;
            out[NN * NC] = (float)loss;
        }
    }
}

// ---------------- launch ----------------
extern "C" void kernel_launch(void* const* d_in, const int* in_sizes, int n_in,
                              void* d_out, int out_size) {
    const float* x = (const float*)d_in[0];
    const void* ei = (const void*)d_in[1];
    const float* ea = (const float*)d_in[2];
    const float* W1 = (const float*)d_in[3];
    const float* b1 = (const float*)d_in[4];
    const float* W2 = (const float*)d_in[5];
    const float* b2 = (const float*)d_in[6];
    float* out = (float*)d_out;

    const int T = 256;
    init_kernel<<<NB, T>>>(ei);
    deg_hist_kernel<<<EB, T>>>(ei, ea);
    scan1_kernel<<<NB, T>>>();
    scan2_kernel<<<NB, T>>>();
    fill_kernel<<<EB, T>>>(ei, ea);
    gemm1_kernel<<<592, T>>>(x, W1);
    gather1_gemm2_kernel<<<(NN * 32 + T - 1) / T, T>>>(b1, W2);
    gather2_softmax_kernel<<<592, T>>>(b2, out);
    edgeloss_kernel<<<ELB, T>>>(ei, ea, out);
}